// round 6
// baseline (speedup 1.0000x reference)
#include <cuda_runtime.h>
#include <cuda_bf16.h>
#include <math.h>
#include <stdint.h>

// Problem constants
#define BATCH 1024
#define SEQ   80
#define UNITS 512
#define EMB   100
#define EMBP  112
#define N4    2048
#define ROWS  (SEQ * BATCH)
#define KC    64              // K-chunk (64 bf16 = 128B rows)

// ---------------- static device scratch ----------------
__device__ float g_X[(size_t)ROWS * EMBP];
__device__ float g_Z1[(size_t)ROWS * N4];          // x@W1 + b1 (reordered cols)
__device__ float g_W1r[EMBP * N4];
__device__ float g_b1r[N4];
__device__ float g_b2r[N4];
// split-bf16 weights, [N][K] K-major (B operand for mma row.col)
__device__ __nv_bfloat16 g_U1hi[(size_t)N4 * UNITS];
__device__ __nv_bfloat16 g_U1lo[(size_t)N4 * UNITS];
__device__ __nv_bfloat16 g_W2hi[(size_t)N4 * 2 * UNITS];
__device__ __nv_bfloat16 g_W2lo[(size_t)N4 * 2 * UNITS];
// split-bf16 hidden states (double buffered), written by epilogue
__device__ __nv_bfloat16 g_h1hi[2][(size_t)BATCH * UNITS];
__device__ __nv_bfloat16 g_h1lo[2][(size_t)BATCH * UNITS];
__device__ __nv_bfloat16 g_h2hi[2][(size_t)BATCH * UNITS];
__device__ __nv_bfloat16 g_h2lo[2][(size_t)BATCH * UNITS];
__device__ float g_c1[(size_t)BATCH * UNITS];
__device__ float g_c2[(size_t)BATCH * UNITS];

__device__ __forceinline__ float sigmoidf_(float x) { return 1.0f / (1.0f + expf(-x)); }

__device__ __forceinline__ uint32_t smem_u32(const void* p) {
    uint32_t a;
    asm("{ .reg .u64 t; cvta.to.shared.u64 t, %1; cvt.u32.u64 %0, t; }" : "=r"(a) : "l"(p));
    return a;
}
__device__ __forceinline__ uint32_t sw_off(uint32_t off) {
    return off ^ ((off >> 3) & 0x70);
}
__device__ __forceinline__ void ldmatrix_x4(uint32_t* r, uint32_t addr) {
    asm volatile("ldmatrix.sync.aligned.m8n8.x4.shared.b16 {%0,%1,%2,%3}, [%4];"
                 : "=r"(r[0]), "=r"(r[1]), "=r"(r[2]), "=r"(r[3]) : "r"(addr));
}
__device__ __forceinline__ void mma16816(float* c, const uint32_t* a, const uint32_t* b) {
    asm volatile("mma.sync.aligned.m16n8k16.row.col.f32.bf16.bf16.f32 "
                 "{%0,%1,%2,%3}, {%4,%5,%6,%7}, {%8,%9}, {%0,%1,%2,%3};"
                 : "+f"(c[0]), "+f"(c[1]), "+f"(c[2]), "+f"(c[3])
                 : "r"(a[0]), "r"(a[1]), "r"(a[2]), "r"(a[3]), "r"(b[0]), "r"(b[1]));
}
__device__ __forceinline__ void cp_async16(uint32_t dst, const void* src) {
    asm volatile("cp.async.cg.shared.global [%0], [%1], 16;" :: "r"(dst), "l"(src) : "memory");
}
#define CP_COMMIT()   asm volatile("cp.async.commit_group;" ::: "memory")
#define CP_WAIT(n)    asm volatile("cp.async.wait_group %0;" :: "n"(n) : "memory")

// ---------------- init states ----------------
__global__ void zero_state_kernel() {
    size_t i = (size_t)blockIdx.x * blockDim.x + threadIdx.x;
    if (i < (size_t)BATCH * UNITS) {
        __nv_bfloat16 z = __float2bfloat16(0.f);
        g_h1hi[0][i] = z; g_h1lo[0][i] = z;
        g_h2hi[0][i] = z; g_h2lo[0][i] = z;
        g_c1[i] = 0.f; g_c2[i] = 0.f;
    }
}

// ---------------- prepack: reorder (n = u*4+g) + bf16 hi/lo split, [N][K] ----------------
__global__ void prepack_kernel(const float* __restrict__ W1, const float* __restrict__ U1,
                               const float* __restrict__ b1, const float* __restrict__ W2,
                               const float* __restrict__ U2, const float* __restrict__ b2) {
    int n = blockIdx.x;
    int u = n >> 2, gg = n & 3;
    int src = gg * UNITS + u;
    for (int k = threadIdx.x; k < 2 * UNITS; k += blockDim.x) {
        float w = (k < UNITS) ? W2[(size_t)k * N4 + src] : U2[(size_t)(k - UNITS) * N4 + src];
        __nv_bfloat16 hi = __float2bfloat16(w);
        g_W2hi[(size_t)n * (2 * UNITS) + k] = hi;
        g_W2lo[(size_t)n * (2 * UNITS) + k] = __float2bfloat16(w - __bfloat162float(hi));
        if (k < UNITS) {
            float v = U1[(size_t)k * N4 + src];
            __nv_bfloat16 h = __float2bfloat16(v);
            g_U1hi[(size_t)n * UNITS + k] = h;
            g_U1lo[(size_t)n * UNITS + k] = __float2bfloat16(v - __bfloat162float(h));
        }
        if (k < EMBP)
            g_W1r[k * N4 + n] = (k < EMB) ? W1[(size_t)k * N4 + src] : 0.f;
    }
    if (threadIdx.x == 0) { g_b1r[n] = b1[src]; g_b2r[n] = b2[src]; }
}

// ---------------- embedding gather ----------------
__global__ void gather_kernel(const int* __restrict__ tokens, const float* __restrict__ emb) {
    int row = blockIdx.x;
    int t = row / BATCH, b = row - t * BATCH;
    int tok = tokens[(size_t)b * SEQ + t];
    int e = threadIdx.x;
    if (e < EMBP)
        g_X[(size_t)row * EMBP + e] = (e < EMB) ? emb[(size_t)tok * EMB + e] : 0.f;
}

// ---------------- pre-GEMM: Z1 = X @ W1r + b1r (fp32 SIMT) ----------------
__global__ __launch_bounds__(256) void pregemm_kernel() {
    __shared__ float As[16][132];
    __shared__ float Bs[16][128];
    int tid = threadIdx.x;
    int mo = blockIdx.y * 128, no = blockIdx.x * 128;
    int tm = (tid >> 4) * 8, tn = (tid & 15) * 8;
    int ar = tid >> 2, ac = (tid & 3) * 4;
    int br = tid >> 5, bc = (tid & 31) * 4;
    float acc[8][8];
#pragma unroll
    for (int i = 0; i < 8; i++)
#pragma unroll
        for (int j = 0; j < 8; j++) acc[i][j] = 0.f;
    for (int k0 = 0; k0 < EMBP; k0 += 16) {
        float4 a0 = *(const float4*)(g_X + (size_t)(mo + ar) * EMBP + k0 + ac);
        float4 a1 = *(const float4*)(g_X + (size_t)(mo + ar + 64) * EMBP + k0 + ac);
        As[ac + 0][ar] = a0.x; As[ac + 1][ar] = a0.y; As[ac + 2][ar] = a0.z; As[ac + 3][ar] = a0.w;
        As[ac + 0][ar + 64] = a1.x; As[ac + 1][ar + 64] = a1.y; As[ac + 2][ar + 64] = a1.z; As[ac + 3][ar + 64] = a1.w;
        *(float4*)&Bs[br][bc]     = *(const float4*)(g_W1r + (size_t)(k0 + br) * N4 + no + bc);
        *(float4*)&Bs[br + 8][bc] = *(const float4*)(g_W1r + (size_t)(k0 + br + 8) * N4 + no + bc);
        __syncthreads();
#pragma unroll
        for (int kk = 0; kk < 16; kk++) {
            float av[8], bv[8];
#pragma unroll
            for (int i = 0; i < 8; i++) av[i] = As[kk][tm + i];
#pragma unroll
            for (int j = 0; j < 8; j++) bv[j] = Bs[kk][tn + j];
#pragma unroll
            for (int i = 0; i < 8; i++)
#pragma unroll
                for (int j = 0; j < 8; j++) acc[i][j] += av[i] * bv[j];
        }
        __syncthreads();
    }
#pragma unroll
    for (int i = 0; i < 8; i++) {
        size_t row = (size_t)(mo + tm + i);
#pragma unroll
        for (int j = 0; j < 8; j++)
            g_Z1[row * N4 + no + tn + j] = acc[i][j] + g_b1r[no + tn + j];
    }
}

// ---------------- HMMA LSTM step: all-bf16 operands, 3-stage cp.async pipeline ----------------
// grid (16, 8), 256 thr = 8 warps (2M x 4N), warp tile 64x32.
// Stage (64KB): Ahi 16K | Alo 16K | Bhi 16K | Blo 16K. 3 stages = 192KB.
#define STAGE_BYTES 65536
#define NSTAGE 3
#define SMEM_DYN (1024 + NSTAGE * STAGE_BYTES)

template <int LAYER>
__global__ __launch_bounds__(256, 1) void lstm_mma_kernel(int t) {
    constexpr int K = (LAYER == 1) ? UNITS : 2 * UNITS;
    constexpr int NC = K / KC;   // 8 or 16

    extern __shared__ char dsm[];
    uint32_t raw = smem_u32(dsm);
    uint32_t pad = (1024u - (raw & 1023u)) & 1023u;
    uint32_t sb = raw + pad;

    int tid = threadIdx.x, wid = tid >> 5, lane = tid & 31;
    int wm = wid >> 2, wn = wid & 3;
    int no = blockIdx.x * 128, mo = blockIdx.y * 128;

    const __nv_bfloat16 *A0hi, *A0lo, *A1hi = nullptr, *A1lo = nullptr;
    __nv_bfloat16 *hhi, *hlo;
    float* cst;
    const __nv_bfloat16 *Bhi, *Blo;
    if (LAYER == 1) {
        A0hi = g_h1hi[t & 1]; A0lo = g_h1lo[t & 1];
        hhi = g_h1hi[(t + 1) & 1]; hlo = g_h1lo[(t + 1) & 1]; cst = g_c1;
        Bhi = g_U1hi; Blo = g_U1lo;
    } else {
        A0hi = g_h1hi[(t + 1) & 1]; A0lo = g_h1lo[(t + 1) & 1];
        A1hi = g_h2hi[t & 1]; A1lo = g_h2lo[t & 1];
        hhi = g_h2hi[(t + 1) & 1]; hlo = g_h2lo[(t + 1) & 1]; cst = g_c2;
        Bhi = g_W2hi; Blo = g_W2lo;
    }

    // per-thread load coords: 8 lines of 16B per 16KB sub-tile laid as 128 rows x 8 lines
    int lr = tid >> 1, lq = (tid & 1) * 4;   // 2 threads per row, 4 lines each

    // issue one chunk's loads into a stage
    auto load_chunk = [&](int i, uint32_t stage) {
        int k0 = i * KC;
        const __nv_bfloat16* ahi = (LAYER == 2 && k0 >= UNITS) ? A1hi : A0hi;
        const __nv_bfloat16* alo = (LAYER == 2 && k0 >= UNITS) ? A1lo : A0lo;
        int kk0 = k0 & (UNITS - 1);
        const __nv_bfloat16* asrc_hi = ahi + (size_t)(mo + lr) * UNITS + kk0 + lq * 8;
        const __nv_bfloat16* asrc_lo = alo + (size_t)(mo + lr) * UNITS + kk0 + lq * 8;
        const __nv_bfloat16* bsrc_hi = Bhi + (size_t)(no + lr) * K + k0 + lq * 8;
        const __nv_bfloat16* bsrc_lo = Blo + (size_t)(no + lr) * K + k0 + lq * 8;
#pragma unroll
        for (int q = 0; q < 4; q++) {
            uint32_t off = sw_off((uint32_t)(lr * 128 + (lq + q) * 16));
            cp_async16(stage + off,         asrc_hi + q * 8);
            cp_async16(stage + 16384 + off, asrc_lo + q * 8);
            cp_async16(stage + 32768 + off, bsrc_hi + q * 8);
            cp_async16(stage + 49152 + off, bsrc_lo + q * 8);
        }
        CP_COMMIT();
    };

    // prologue: fill all 3 stages
#pragma unroll
    for (int s = 0; s < NSTAGE; s++)
        load_chunk(s, sb + (uint32_t)s * STAGE_BYTES);

    float acc[4][4][4];
#pragma unroll
    for (int a = 0; a < 4; a++)
#pragma unroll
        for (int b = 0; b < 4; b++)
#pragma unroll
            for (int cc = 0; cc < 4; cc++) acc[a][b][cc] = 0.f;

    // ldmatrix lane-row offsets
    uint32_t a_rowoff[4];
#pragma unroll
    for (int mt = 0; mt < 4; mt++)
        a_rowoff[mt] = (uint32_t)((wm * 64 + mt * 16 + (lane & 15)) * 128 + (lane >> 4) * 16);
    uint32_t b_rowoff[2];
#pragma unroll
    for (int pr = 0; pr < 2; pr++)
        b_rowoff[pr] = (uint32_t)((wn * 32 + pr * 16 + ((lane >> 4) & 1) * 8 + (lane & 7)) * 128 + ((lane >> 3) & 1) * 16);

    for (int i = 0; i < NC; i++) {
        uint32_t cur = sb + (uint32_t)(i % NSTAGE) * STAGE_BYTES;

        // wait until chunk i's loads landed (leave up to 2 newer groups in flight)
        if (i + 1 >= NC)      CP_WAIT(0);
        else if (i + 2 >= NC) CP_WAIT(1);
        else                  CP_WAIT(2);
        __syncthreads();

#pragma unroll
        for (int ks = 0; ks < 4; ks++) {
            uint32_t ahi[4][4], alo[4][4], bhi[2][4], blo[2][4];
#pragma unroll
            for (int mt = 0; mt < 4; mt++) {
                uint32_t off = sw_off(a_rowoff[mt] + ks * 32);
                ldmatrix_x4(ahi[mt], cur + off);
                ldmatrix_x4(alo[mt], cur + 16384 + off);
            }
#pragma unroll
            for (int pr = 0; pr < 2; pr++) {
                uint32_t off = sw_off(b_rowoff[pr] + ks * 32);
                ldmatrix_x4(bhi[pr], cur + 32768 + off);
                ldmatrix_x4(blo[pr], cur + 49152 + off);
            }
#pragma unroll
            for (int mt = 0; mt < 4; mt++)
#pragma unroll
                for (int nt = 0; nt < 4; nt++) {
                    const uint32_t* bh = &bhi[nt >> 1][(nt & 1) * 2];
                    const uint32_t* bl = &blo[nt >> 1][(nt & 1) * 2];
                    mma16816(acc[mt][nt], ahi[mt], bh);
                    mma16816(acc[mt][nt], ahi[mt], bl);
                    mma16816(acc[mt][nt], alo[mt], bh);
                }
        }
        __syncthreads();   // stage consumed; safe to overwrite

        if (i + NSTAGE < NC)
            load_chunk(i + NSTAGE, cur);
    }

    // ---- fused LSTM gate epilogue ----
    // acc frag: {r0c0, r0c1, r1c0, r1c1}; even lanes (i,f), odd lanes (g,o) -> shfl_xor(1)
#pragma unroll
    for (int mt = 0; mt < 4; mt++)
#pragma unroll
        for (int nt = 0; nt < 4; nt++)
#pragma unroll
            for (int ri = 0; ri < 2; ri++) {
                float v0 = acc[mt][nt][2 * ri + 0];
                float v1 = acc[mt][nt][2 * ri + 1];
                float o0 = __shfl_xor_sync(0xFFFFFFFF, v0, 1);
                float o1 = __shfl_xor_sync(0xFFFFFFFF, v1, 1);
                if ((lane & 1) == 0) {
                    int row = mo + wm * 64 + mt * 16 + (lane >> 2) + ri * 8;
                    int c_abs = no + wn * 32 + nt * 8 + (lane & 3) * 2;
                    const float* zp = (LAYER == 1)
                        ? (g_Z1 + (size_t)t * BATCH * N4 + (size_t)row * N4 + c_abs)
                        : (g_b2r + c_abs);
                    float4 zb = *(const float4*)zp;
                    float zi = v0 + zb.x, zf = v1 + zb.y;
                    float zg = o0 + zb.z, zo = o1 + zb.w;
                    int u = c_abs >> 2;
                    size_t idx = (size_t)row * UNITS + u;
                    float cn = sigmoidf_(zf) * cst[idx] + sigmoidf_(zi) * tanhf(zg);
                    cst[idx] = cn;
                    float hv = sigmoidf_(zo) * tanhf(cn);
                    __nv_bfloat16 hh = __float2bfloat16(hv);
                    hhi[idx] = hh;
                    hlo[idx] = __float2bfloat16(hv - __bfloat162float(hh));
                }
            }
}

// ---------------- output projection ----------------
__global__ void out_kernel(const float* __restrict__ Wout, const float* __restrict__ bout,
                           float* __restrict__ out, int parity) {
    int gw = (blockIdx.x * blockDim.x + threadIdx.x) >> 5;
    int lane = threadIdx.x & 31;
    if (gw >= BATCH) return;
    const __nv_bfloat16* hh = g_h2hi[parity] + (size_t)gw * UNITS;
    const __nv_bfloat16* hl = g_h2lo[parity] + (size_t)gw * UNITS;
    float s = 0.f;
    for (int k = lane; k < UNITS; k += 32)
        s += (__bfloat162float(hh[k]) + __bfloat162float(hl[k])) * Wout[k];
#pragma unroll
    for (int off = 16; off > 0; off >>= 1) s += __shfl_xor_sync(0xFFFFFFFF, s, off);
    if (lane == 0) out[gw] = sigmoidf_(s + bout[0]);
}

// ---------------- launch ----------------
extern "C" void kernel_launch(void* const* d_in, const int* in_sizes, int n_in,
                              void* d_out, int out_size) {
    const int*   tokens = (const int*)d_in[0];
    const float* emb    = (const float*)d_in[1];
    const float* W1     = (const float*)d_in[2];
    const float* U1     = (const float*)d_in[3];
    const float* b1     = (const float*)d_in[4];
    const float* W2     = (const float*)d_in[5];
    const float* U2     = (const float*)d_in[6];
    const float* b2     = (const float*)d_in[7];
    const float* Wout   = (const float*)d_in[8];
    const float* bout   = (const float*)d_in[9];
    float* out = (float*)d_out;

    cudaFuncSetAttribute(lstm_mma_kernel<1>, cudaFuncAttributeMaxDynamicSharedMemorySize, SMEM_DYN);
    cudaFuncSetAttribute(lstm_mma_kernel<2>, cudaFuncAttributeMaxDynamicSharedMemorySize, SMEM_DYN);

    zero_state_kernel<<<(BATCH * UNITS + 255) / 256, 256>>>();
    prepack_kernel<<<N4, 256>>>(W1, U1, b1, W2, U2, b2);
    gather_kernel<<<ROWS, 128>>>(tokens, emb);
    pregemm_kernel<<<dim3(N4 / 128, ROWS / 128), 256>>>();

    for (int t = 0; t < SEQ; t++) {
        lstm_mma_kernel<1><<<dim3(16, 8), 256, SMEM_DYN>>>(t);
        lstm_mma_kernel<2><<<dim3(16, 8), 256, SMEM_DYN>>>(t);
    }
    out_kernel<<<(BATCH * 32 + 255) / 256, 256>>>(Wout, bout, out, SEQ & 1);
}

// round 7
// speedup vs baseline: 1.4309x; 1.4309x over previous
#include <cuda_runtime.h>
#include <cuda_bf16.h>
#include <math.h>
#include <stdint.h>

// Problem constants
#define BATCH 1024
#define SEQ   80
#define UNITS 512
#define EMB   100
#define EMBP  112
#define N4    2048
#define ROWS  (SEQ * BATCH)
#define KC    64              // K-chunk (64 bf16 = 128B rows)

// ---------------- static device scratch ----------------
__device__ float g_X[(size_t)ROWS * EMBP];
__device__ float g_Z1[(size_t)ROWS * N4];          // x@W1 + b1 (reordered cols)
__device__ float g_W1r[EMBP * N4];
__device__ float g_b1r[N4];
__device__ float g_b2r[N4];
// bf16 weights, [N][K] K-major (B operand for mma row.col)
__device__ __nv_bfloat16 g_U1b[(size_t)N4 * UNITS];
__device__ __nv_bfloat16 g_W2b[(size_t)N4 * 2 * UNITS];
// bf16 hidden states (double buffered), written by epilogue
__device__ __nv_bfloat16 g_h1b[2][(size_t)BATCH * UNITS];
__device__ __nv_bfloat16 g_h2b[2][(size_t)BATCH * UNITS];
__device__ float g_c1[(size_t)BATCH * UNITS];
__device__ float g_c2[(size_t)BATCH * UNITS];

__device__ __forceinline__ float sigmoidf_(float x) { return 1.0f / (1.0f + expf(-x)); }

__device__ __forceinline__ uint32_t smem_u32(const void* p) {
    uint32_t a;
    asm("{ .reg .u64 t; cvta.to.shared.u64 t, %1; cvt.u32.u64 %0, t; }" : "=r"(a) : "l"(p));
    return a;
}
__device__ __forceinline__ uint32_t sw_off(uint32_t off) {
    return off ^ ((off >> 3) & 0x70);
}
__device__ __forceinline__ void ldmatrix_x4(uint32_t* r, uint32_t addr) {
    asm volatile("ldmatrix.sync.aligned.m8n8.x4.shared.b16 {%0,%1,%2,%3}, [%4];"
                 : "=r"(r[0]), "=r"(r[1]), "=r"(r[2]), "=r"(r[3]) : "r"(addr));
}
__device__ __forceinline__ void mma16816(float* c, const uint32_t* a, const uint32_t* b) {
    asm volatile("mma.sync.aligned.m16n8k16.row.col.f32.bf16.bf16.f32 "
                 "{%0,%1,%2,%3}, {%4,%5,%6,%7}, {%8,%9}, {%0,%1,%2,%3};"
                 : "+f"(c[0]), "+f"(c[1]), "+f"(c[2]), "+f"(c[3])
                 : "r"(a[0]), "r"(a[1]), "r"(a[2]), "r"(a[3]), "r"(b[0]), "r"(b[1]));
}
__device__ __forceinline__ void cp_async16(uint32_t dst, const void* src) {
    asm volatile("cp.async.cg.shared.global [%0], [%1], 16;" :: "r"(dst), "l"(src) : "memory");
}
#define CP_COMMIT()   asm volatile("cp.async.commit_group;" ::: "memory")
#define CP_WAIT(n)    asm volatile("cp.async.wait_group %0;" :: "n"(n) : "memory")

// ---------------- init states ----------------
__global__ void zero_state_kernel() {
    size_t i = (size_t)blockIdx.x * blockDim.x + threadIdx.x;
    if (i < (size_t)BATCH * UNITS) {
        __nv_bfloat16 z = __float2bfloat16(0.f);
        g_h1b[0][i] = z; g_h2b[0][i] = z;
        g_c1[i] = 0.f; g_c2[i] = 0.f;
    }
}

// ---------------- prepack: reorder (n = u*4+g) + bf16, [N][K] ----------------
__global__ void prepack_kernel(const float* __restrict__ W1, const float* __restrict__ U1,
                               const float* __restrict__ b1, const float* __restrict__ W2,
                               const float* __restrict__ U2, const float* __restrict__ b2) {
    int n = blockIdx.x;
    int u = n >> 2, gg = n & 3;
    int src = gg * UNITS + u;
    for (int k = threadIdx.x; k < 2 * UNITS; k += blockDim.x) {
        float w = (k < UNITS) ? W2[(size_t)k * N4 + src] : U2[(size_t)(k - UNITS) * N4 + src];
        g_W2b[(size_t)n * (2 * UNITS) + k] = __float2bfloat16(w);
        if (k < UNITS)
            g_U1b[(size_t)n * UNITS + k] = __float2bfloat16(U1[(size_t)k * N4 + src]);
        if (k < EMBP)
            g_W1r[k * N4 + n] = (k < EMB) ? W1[(size_t)k * N4 + src] : 0.f;
    }
    if (threadIdx.x == 0) { g_b1r[n] = b1[src]; g_b2r[n] = b2[src]; }
}

// ---------------- embedding gather ----------------
__global__ void gather_kernel(const int* __restrict__ tokens, const float* __restrict__ emb) {
    int row = blockIdx.x;
    int t = row / BATCH, b = row - t * BATCH;
    int tok = tokens[(size_t)b * SEQ + t];
    int e = threadIdx.x;
    if (e < EMBP)
        g_X[(size_t)row * EMBP + e] = (e < EMB) ? emb[(size_t)tok * EMB + e] : 0.f;
}

// ---------------- pre-GEMM: Z1 = X @ W1r + b1r (fp32 SIMT) ----------------
__global__ __launch_bounds__(256) void pregemm_kernel() {
    __shared__ float As[16][132];
    __shared__ float Bs[16][128];
    int tid = threadIdx.x;
    int mo = blockIdx.y * 128, no = blockIdx.x * 128;
    int tm = (tid >> 4) * 8, tn = (tid & 15) * 8;
    int ar = tid >> 2, ac = (tid & 3) * 4;
    int br = tid >> 5, bc = (tid & 31) * 4;
    float acc[8][8];
#pragma unroll
    for (int i = 0; i < 8; i++)
#pragma unroll
        for (int j = 0; j < 8; j++) acc[i][j] = 0.f;
    for (int k0 = 0; k0 < EMBP; k0 += 16) {
        float4 a0 = *(const float4*)(g_X + (size_t)(mo + ar) * EMBP + k0 + ac);
        float4 a1 = *(const float4*)(g_X + (size_t)(mo + ar + 64) * EMBP + k0 + ac);
        As[ac + 0][ar] = a0.x; As[ac + 1][ar] = a0.y; As[ac + 2][ar] = a0.z; As[ac + 3][ar] = a0.w;
        As[ac + 0][ar + 64] = a1.x; As[ac + 1][ar + 64] = a1.y; As[ac + 2][ar + 64] = a1.z; As[ac + 3][ar + 64] = a1.w;
        *(float4*)&Bs[br][bc]     = *(const float4*)(g_W1r + (size_t)(k0 + br) * N4 + no + bc);
        *(float4*)&Bs[br + 8][bc] = *(const float4*)(g_W1r + (size_t)(k0 + br + 8) * N4 + no + bc);
        __syncthreads();
#pragma unroll
        for (int kk = 0; kk < 16; kk++) {
            float av[8], bv[8];
#pragma unroll
            for (int i = 0; i < 8; i++) av[i] = As[kk][tm + i];
#pragma unroll
            for (int j = 0; j < 8; j++) bv[j] = Bs[kk][tn + j];
#pragma unroll
            for (int i = 0; i < 8; i++)
#pragma unroll
                for (int j = 0; j < 8; j++) acc[i][j] += av[i] * bv[j];
        }
        __syncthreads();
    }
#pragma unroll
    for (int i = 0; i < 8; i++) {
        size_t row = (size_t)(mo + tm + i);
#pragma unroll
        for (int j = 0; j < 8; j++)
            g_Z1[row * N4 + no + tn + j] = acc[i][j] + g_b1r[no + tn + j];
    }
}

// ---------------- HMMA LSTM step: single-pass bf16, 2-stage pipeline ----------------
// grid (16, 8), 256 thr = 8 warps (2M x 4N), warp tile 64x32.
// Stage (32KB): A 16K | B 16K. Double buffered = 64KB.
#define STAGE_BYTES 32768
#define SMEM_DYN    (1024 + 2 * STAGE_BYTES)

template <int LAYER>
__global__ __launch_bounds__(256, 1) void lstm_mma_kernel(int t) {
    constexpr int K = (LAYER == 1) ? UNITS : 2 * UNITS;
    constexpr int NC = K / KC;   // 8 or 16

    extern __shared__ char dsm[];
    uint32_t raw = smem_u32(dsm);
    uint32_t pad = (1024u - (raw & 1023u)) & 1023u;
    uint32_t sb = raw + pad;

    int tid = threadIdx.x, wid = tid >> 5, lane = tid & 31;
    int wm = wid >> 2, wn = wid & 3;
    int no = blockIdx.x * 128, mo = blockIdx.y * 128;

    const __nv_bfloat16 *A0, *A1 = nullptr;
    __nv_bfloat16* hout;
    float* cst;
    const __nv_bfloat16* Bw;
    if (LAYER == 1) {
        A0 = g_h1b[t & 1];
        hout = g_h1b[(t + 1) & 1]; cst = g_c1;
        Bw = g_U1b;
    } else {
        A0 = g_h1b[(t + 1) & 1]; A1 = g_h2b[t & 1];
        hout = g_h2b[(t + 1) & 1]; cst = g_c2;
        Bw = g_W2b;
    }

    // per-thread load coords: 2 threads per 128B row, 4 x 16B lines each
    int lr = tid >> 1, lq = (tid & 1) * 4;

    auto load_chunk = [&](int i, uint32_t stage) {
        int k0 = i * KC;
        const __nv_bfloat16* asrc = (LAYER == 2 && k0 >= UNITS) ? A1 : A0;
        int kk0 = k0 & (UNITS - 1);
        const __nv_bfloat16* ap = asrc + (size_t)(mo + lr) * UNITS + kk0 + lq * 8;
        const __nv_bfloat16* bp = Bw + (size_t)(no + lr) * K + k0 + lq * 8;
#pragma unroll
        for (int q = 0; q < 4; q++) {
            uint32_t off = sw_off((uint32_t)(lr * 128 + (lq + q) * 16));
            cp_async16(stage + off,         ap + q * 8);
            cp_async16(stage + 16384 + off, bp + q * 8);
        }
        CP_COMMIT();
    };

    float acc[4][4][4];
#pragma unroll
    for (int a = 0; a < 4; a++)
#pragma unroll
        for (int b = 0; b < 4; b++)
#pragma unroll
            for (int cc = 0; cc < 4; cc++) acc[a][b][cc] = 0.f;

    // ldmatrix lane-row offsets
    uint32_t a_rowoff[4];
#pragma unroll
    for (int mt = 0; mt < 4; mt++)
        a_rowoff[mt] = (uint32_t)((wm * 64 + mt * 16 + (lane & 15)) * 128 + (lane >> 4) * 16);
    uint32_t b_rowoff[2];
#pragma unroll
    for (int pr = 0; pr < 2; pr++)
        b_rowoff[pr] = (uint32_t)((wn * 32 + pr * 16 + ((lane >> 4) & 1) * 8 + (lane & 7)) * 128 + ((lane >> 3) & 1) * 16);

    // prologue: chunk 0
    load_chunk(0, sb);
    CP_WAIT(0);
    __syncthreads();

    for (int i = 0; i < NC; i++) {
        uint32_t cur = sb + (uint32_t)(i & 1) * STAGE_BYTES;
        uint32_t nxt = sb + (uint32_t)((i + 1) & 1) * STAGE_BYTES;

        if (i + 1 < NC)
            load_chunk(i + 1, nxt);   // overlaps with MMA below

#pragma unroll
        for (int ks = 0; ks < 4; ks++) {
            uint32_t af[4][4], bf[2][4];
#pragma unroll
            for (int mt = 0; mt < 4; mt++)
                ldmatrix_x4(af[mt], cur + sw_off(a_rowoff[mt] + ks * 32));
#pragma unroll
            for (int pr = 0; pr < 2; pr++)
                ldmatrix_x4(bf[pr], cur + 16384 + sw_off(b_rowoff[pr] + ks * 32));
#pragma unroll
            for (int mt = 0; mt < 4; mt++)
#pragma unroll
                for (int nt = 0; nt < 4; nt++)
                    mma16816(acc[mt][nt], af[mt], &bf[nt >> 1][(nt & 1) * 2]);
        }

        if (i + 1 < NC) CP_WAIT(0);
        __syncthreads();
    }

    // ---- fused LSTM gate epilogue ----
    // acc frag: {r0c0, r0c1, r1c0, r1c1}; even lanes (i,f), odd lanes (g,o) -> shfl_xor(1)
#pragma unroll
    for (int mt = 0; mt < 4; mt++)
#pragma unroll
        for (int nt = 0; nt < 4; nt++)
#pragma unroll
            for (int ri = 0; ri < 2; ri++) {
                float v0 = acc[mt][nt][2 * ri + 0];
                float v1 = acc[mt][nt][2 * ri + 1];
                float o0 = __shfl_xor_sync(0xFFFFFFFF, v0, 1);
                float o1 = __shfl_xor_sync(0xFFFFFFFF, v1, 1);
                if ((lane & 1) == 0) {
                    int row = mo + wm * 64 + mt * 16 + (lane >> 2) + ri * 8;
                    int c_abs = no + wn * 32 + nt * 8 + (lane & 3) * 2;
                    const float* zp = (LAYER == 1)
                        ? (g_Z1 + (size_t)t * BATCH * N4 + (size_t)row * N4 + c_abs)
                        : (g_b2r + c_abs);
                    float4 zb = *(const float4*)zp;
                    float zi = v0 + zb.x, zf = v1 + zb.y;
                    float zg = o0 + zb.z, zo = o1 + zb.w;
                    int u = c_abs >> 2;
                    size_t idx = (size_t)row * UNITS + u;
                    float cn = sigmoidf_(zf) * cst[idx] + sigmoidf_(zi) * tanhf(zg);
                    cst[idx] = cn;
                    hout[idx] = __float2bfloat16(sigmoidf_(zo) * tanhf(cn));
                }
            }
}

// ---------------- output projection ----------------
__global__ void out_kernel(const float* __restrict__ Wout, const float* __restrict__ bout,
                           float* __restrict__ out, int parity) {
    int gw = (blockIdx.x * blockDim.x + threadIdx.x) >> 5;
    int lane = threadIdx.x & 31;
    if (gw >= BATCH) return;
    const __nv_bfloat16* h = g_h2b[parity] + (size_t)gw * UNITS;
    float s = 0.f;
    for (int k = lane; k < UNITS; k += 32)
        s += __bfloat162float(h[k]) * Wout[k];
#pragma unroll
    for (int off = 16; off > 0; off >>= 1) s += __shfl_xor_sync(0xFFFFFFFF, s, off);
    if (lane == 0) out[gw] = sigmoidf_(s + bout[0]);
}

// ---------------- launch ----------------
extern "C" void kernel_launch(void* const* d_in, const int* in_sizes, int n_in,
                              void* d_out, int out_size) {
    const int*   tokens = (const int*)d_in[0];
    const float* emb    = (const float*)d_in[1];
    const float* W1     = (const float*)d_in[2];
    const float* U1     = (const float*)d_in[3];
    const float* b1     = (const float*)d_in[4];
    const float* W2     = (const float*)d_in[5];
    const float* U2     = (const float*)d_in[6];
    const float* b2     = (const float*)d_in[7];
    const float* Wout   = (const float*)d_in[8];
    const float* bout   = (const float*)d_in[9];
    float* out = (float*)d_out;

    cudaFuncSetAttribute(lstm_mma_kernel<1>, cudaFuncAttributeMaxDynamicSharedMemorySize, SMEM_DYN);
    cudaFuncSetAttribute(lstm_mma_kernel<2>, cudaFuncAttributeMaxDynamicSharedMemorySize, SMEM_DYN);

    zero_state_kernel<<<(BATCH * UNITS + 255) / 256, 256>>>();
    prepack_kernel<<<N4, 256>>>(W1, U1, b1, W2, U2, b2);
    gather_kernel<<<ROWS, 128>>>(tokens, emb);
    pregemm_kernel<<<dim3(N4 / 128, ROWS / 128), 256>>>();

    for (int t = 0; t < SEQ; t++) {
        lstm_mma_kernel<1><<<dim3(16, 8), 256, SMEM_DYN>>>(t);
        lstm_mma_kernel<2><<<dim3(16, 8), 256, SMEM_DYN>>>(t);
    }
    out_kernel<<<(BATCH * 32 + 255) / 256, 256>>>(Wout, bout, out, SEQ & 1);
}

// round 8
// speedup vs baseline: 1.5336x; 1.0717x over previous
#include <cuda_runtime.h>
#include <cuda_bf16.h>
#include <math.h>
#include <stdint.h>

// Problem constants
#define BATCH 1024
#define SEQ   80
#define UNITS 512
#define EMB   100
#define N4    2048
#define ROWS  (SEQ * BATCH)
#define KC    64               // K-chunk (64 bf16 = 128B rows)
#define NBLK  128              // persistent grid size (<=148 SMs -> all resident)

// ---------------- static device scratch ----------------
__device__ __nv_bfloat16 g_Xb[(size_t)ROWS * 128];     // gathered embeddings, bf16, padded K=128
__device__ float g_Z1[(size_t)ROWS * N4];              // x@W1 + b1 (reordered cols, fp32)
__device__ __nv_bfloat16 g_W1b[(size_t)N4 * 128];      // W1 reordered, [N][K] bf16, K padded
__device__ float g_b1r[N4];
__device__ float g_b2r[N4];
__device__ __nv_bfloat16 g_U1b[(size_t)N4 * UNITS];    // U1 reordered, [N][K]
__device__ __nv_bfloat16 g_W2b[(size_t)N4 * 2 * UNITS];// [W2;U2] reordered, [N][K]
__device__ __nv_bfloat16 g_h1b[2][(size_t)BATCH * UNITS];
__device__ __nv_bfloat16 g_h2b[2][(size_t)BATCH * UNITS];
__device__ unsigned g_bar_count;
__device__ unsigned g_bar_gen;

__device__ __forceinline__ float sigmoidf_(float x) { return __fdividef(1.0f, 1.0f + __expf(-x)); }

__device__ __forceinline__ uint32_t smem_u32(const void* p) {
    uint32_t a;
    asm("{ .reg .u64 t; cvta.to.shared.u64 t, %1; cvt.u32.u64 %0, t; }" : "=r"(a) : "l"(p));
    return a;
}
__device__ __forceinline__ uint32_t sw_off(uint32_t off) {
    return off ^ ((off >> 3) & 0x70);
}
__device__ __forceinline__ void ldmatrix_x4(uint32_t* r, uint32_t addr) {
    asm volatile("ldmatrix.sync.aligned.m8n8.x4.shared.b16 {%0,%1,%2,%3}, [%4];"
                 : "=r"(r[0]), "=r"(r[1]), "=r"(r[2]), "=r"(r[3]) : "r"(addr));
}
__device__ __forceinline__ void mma16816(float* c, const uint32_t* a, const uint32_t* b) {
    asm volatile("mma.sync.aligned.m16n8k16.row.col.f32.bf16.bf16.f32 "
                 "{%0,%1,%2,%3}, {%4,%5,%6,%7}, {%8,%9}, {%0,%1,%2,%3};"
                 : "+f"(c[0]), "+f"(c[1]), "+f"(c[2]), "+f"(c[3])
                 : "r"(a[0]), "r"(a[1]), "r"(a[2]), "r"(a[3]), "r"(b[0]), "r"(b[1]));
}
__device__ __forceinline__ void cp_async16(uint32_t dst, const void* src) {
    asm volatile("cp.async.cg.shared.global [%0], [%1], 16;" :: "r"(dst), "l"(src) : "memory");
}
#define CP_COMMIT()   asm volatile("cp.async.commit_group;" ::: "memory")
#define CP_WAIT(n)    asm volatile("cp.async.wait_group %0;" :: "n"(n) : "memory")

// ---------------- reset (per replay; determinism) ----------------
__global__ void reset_kernel() {
    if (threadIdx.x == 0) { g_bar_count = 0; g_bar_gen = 0; }
}

// ---------------- prepack: reorder (n = u*4+g) + bf16, [N][K] ----------------
__global__ void prepack_kernel(const float* __restrict__ W1, const float* __restrict__ U1,
                               const float* __restrict__ b1, const float* __restrict__ W2,
                               const float* __restrict__ U2, const float* __restrict__ b2) {
    int n = blockIdx.x;
    int u = n >> 2, gg = n & 3;
    int src = gg * UNITS + u;
    for (int k = threadIdx.x; k < 2 * UNITS; k += blockDim.x) {
        float w = (k < UNITS) ? W2[(size_t)k * N4 + src] : U2[(size_t)(k - UNITS) * N4 + src];
        g_W2b[(size_t)n * (2 * UNITS) + k] = __float2bfloat16(w);
        if (k < UNITS)
            g_U1b[(size_t)n * UNITS + k] = __float2bfloat16(U1[(size_t)k * N4 + src]);
        if (k < 128)
            g_W1b[(size_t)n * 128 + k] = __float2bfloat16(k < EMB ? W1[(size_t)k * N4 + src] : 0.f);
    }
    if (threadIdx.x == 0) { g_b1r[n] = b1[src]; g_b2r[n] = b2[src]; }
}

// ---------------- embedding gather (bf16, padded to 128 cols) ----------------
__global__ void gather_kernel(const int* __restrict__ tokens, const float* __restrict__ emb) {
    int row = blockIdx.x;
    int t = row / BATCH, b = row - t * BATCH;
    int tok = tokens[(size_t)b * SEQ + t];
    int e = threadIdx.x;
    g_Xb[(size_t)row * 128 + e] = __float2bfloat16(e < EMB ? emb[(size_t)tok * EMB + e] : 0.f);
}

// ---------------- shared HMMA mainloop: 128x128 tile, 2-stage cp.async ----------------
// Stage (32KB): A 16K | B 16K. 8 warps (2M x 4N), warp tile 64x32.
#define STAGE_BYTES 32768

__device__ __forceinline__ void mma_mainloop(
    float (&acc)[4][4][4], uint32_t sb,
    const __nv_bfloat16* __restrict__ A0, const __nv_bfloat16* __restrict__ A1, int astride,
    const __nv_bfloat16* __restrict__ Bw, int bstride, int mo, int no, int nc)
{
    int tid = threadIdx.x, wid = tid >> 5, lane = tid & 31;
    int wm = wid >> 2, wn = wid & 3;
    int lr = tid >> 1, lq = (tid & 1) * 4;

    auto load_chunk = [&](int i, uint32_t stage) {
        int k0 = i * KC;
        const __nv_bfloat16* asrc = (A1 != nullptr && k0 >= UNITS) ? A1 : A0;
        int kk0 = k0 & (UNITS - 1);
        const __nv_bfloat16* ap = asrc + (size_t)(mo + lr) * astride + kk0 + lq * 8;
        const __nv_bfloat16* bp = Bw + (size_t)(no + lr) * bstride + k0 + lq * 8;
#pragma unroll
        for (int q = 0; q < 4; q++) {
            uint32_t off = sw_off((uint32_t)(lr * 128 + (lq + q) * 16));
            cp_async16(stage + off,         ap + q * 8);
            cp_async16(stage + 16384 + off, bp + q * 8);
        }
        CP_COMMIT();
    };

    uint32_t a_rowoff[4];
#pragma unroll
    for (int mt = 0; mt < 4; mt++)
        a_rowoff[mt] = (uint32_t)((wm * 64 + mt * 16 + (lane & 15)) * 128 + (lane >> 4) * 16);
    uint32_t b_rowoff[2];
#pragma unroll
    for (int pr = 0; pr < 2; pr++)
        b_rowoff[pr] = (uint32_t)((wn * 32 + pr * 16 + ((lane >> 4) & 1) * 8 + (lane & 7)) * 128 + ((lane >> 3) & 1) * 16);

    load_chunk(0, sb);
    CP_WAIT(0);
    __syncthreads();

    for (int i = 0; i < nc; i++) {
        uint32_t cur = sb + (uint32_t)(i & 1) * STAGE_BYTES;
        uint32_t nxt = sb + (uint32_t)((i + 1) & 1) * STAGE_BYTES;

        if (i + 1 < nc)
            load_chunk(i + 1, nxt);

#pragma unroll
        for (int ks = 0; ks < 4; ks++) {
            uint32_t af[4][4], bf[2][4];
#pragma unroll
            for (int mt = 0; mt < 4; mt++)
                ldmatrix_x4(af[mt], cur + sw_off(a_rowoff[mt] + ks * 32));
#pragma unroll
            for (int pr = 0; pr < 2; pr++)
                ldmatrix_x4(bf[pr], cur + 16384 + sw_off(b_rowoff[pr] + ks * 32));
#pragma unroll
            for (int mt = 0; mt < 4; mt++)
#pragma unroll
                for (int nt = 0; nt < 4; nt++)
                    mma16816(acc[mt][nt], af[mt], &bf[nt >> 1][(nt & 1) * 2]);
        }

        if (i + 1 < nc) CP_WAIT(0);
        __syncthreads();
    }
}

// ---------------- pre-GEMM (bf16 HMMA): Z1 = Xb @ W1b + b1r ----------------
#define SMEM_PRE (1024 + 2 * STAGE_BYTES)

__global__ __launch_bounds__(256) void pregemm_hmma_kernel() {
    extern __shared__ char dsm[];
    uint32_t raw = smem_u32(dsm);
    uint32_t sb = raw + ((1024u - (raw & 1023u)) & 1023u);

    int lane = threadIdx.x & 31, wid = threadIdx.x >> 5;
    int wm = wid >> 2, wn = wid & 3;
    int mo = blockIdx.y * 128, no = blockIdx.x * 128;

    float acc[4][4][4];
#pragma unroll
    for (int a = 0; a < 4; a++)
#pragma unroll
        for (int b = 0; b < 4; b++)
#pragma unroll
            for (int cc = 0; cc < 4; cc++) acc[a][b][cc] = 0.f;

    mma_mainloop(acc, sb, g_Xb, nullptr, 128, g_W1b, 128, mo, no, 2);

#pragma unroll
    for (int mt = 0; mt < 4; mt++)
#pragma unroll
        for (int nt = 0; nt < 4; nt++)
#pragma unroll
            for (int ri = 0; ri < 2; ri++) {
                float v0 = acc[mt][nt][2 * ri + 0];
                float v1 = acc[mt][nt][2 * ri + 1];
                float o0 = __shfl_xor_sync(0xFFFFFFFF, v0, 1);
                float o1 = __shfl_xor_sync(0xFFFFFFFF, v1, 1);
                if ((lane & 1) == 0) {
                    int row_l = wm * 64 + mt * 16 + (lane >> 2) + ri * 8;
                    int c_l = wn * 32 + nt * 8 + (lane & 3) * 2;   // multiple of 4
                    float4 bb = *(const float4*)(g_b1r + no + c_l);
                    float4 r = make_float4(v0 + bb.x, v1 + bb.y, o0 + bb.z, o1 + bb.w);
                    *(float4*)(g_Z1 + ((size_t)mo + row_l) * N4 + no + c_l) = r;
                }
            }
}

// ---------------- LSTM gate epilogue (c in SMEM, h -> global bf16) ----------------
template <int LAYER>
__device__ __forceinline__ void lstm_epilogue(
    float (&acc)[4][4][4], int t, int mo, int no,
    float* __restrict__ csm, __nv_bfloat16* __restrict__ hout)
{
    int lane = threadIdx.x & 31, wid = threadIdx.x >> 5;
    int wm = wid >> 2, wn = wid & 3;
#pragma unroll
    for (int mt = 0; mt < 4; mt++)
#pragma unroll
        for (int nt = 0; nt < 4; nt++)
#pragma unroll
            for (int ri = 0; ri < 2; ri++) {
                float v0 = acc[mt][nt][2 * ri + 0];
                float v1 = acc[mt][nt][2 * ri + 1];
                float o0 = __shfl_xor_sync(0xFFFFFFFF, v0, 1);
                float o1 = __shfl_xor_sync(0xFFFFFFFF, v1, 1);
                if ((lane & 1) == 0) {
                    int row_l = wm * 64 + mt * 16 + (lane >> 2) + ri * 8;
                    int c_l = wn * 32 + nt * 8 + (lane & 3) * 2;   // multiple of 4
                    const float* zp = (LAYER == 1)
                        ? (g_Z1 + ((size_t)t * BATCH + mo + row_l) * N4 + no + c_l)
                        : (g_b2r + no + c_l);
                    float4 zb = *(const float4*)zp;
                    float zi = v0 + zb.x, zf = v1 + zb.y;
                    float zg = o0 + zb.z, zo = o1 + zb.w;
                    float* cp = csm + row_l * 32 + (c_l >> 2);
                    float cn = sigmoidf_(zf) * (*cp) + sigmoidf_(zi) * tanhf(zg);
                    *cp = cn;
                    hout[(size_t)(mo + row_l) * UNITS + ((no + c_l) >> 2)] =
                        __float2bfloat16(sigmoidf_(zo) * tanhf(cn));
                }
            }
}

// ---------------- persistent LSTM kernel: all 80 steps, grid barrier ----------------
#define SMEM_PERSIST (1024 + 2 * STAGE_BYTES + 2 * 16384)

__device__ __forceinline__ void grid_barrier(unsigned target) {
    __threadfence();
    __syncthreads();
    if (threadIdx.x == 0) {
        unsigned ticket = atomicAdd(&g_bar_count, 1u);
        if (ticket == NBLK - 1) {
            atomicExch(&g_bar_count, 0u);
            __threadfence();
            atomicAdd(&g_bar_gen, 1u);
        } else {
            while (*(volatile unsigned*)&g_bar_gen < target) { }
            __threadfence();
        }
    }
    __syncthreads();
}

__global__ __launch_bounds__(256, 1) void lstm_persist_kernel() {
    extern __shared__ char dsm[];
    uint32_t raw = smem_u32(dsm);
    uint32_t pad = (1024u - (raw & 1023u)) & 1023u;
    uint32_t sb = raw + pad;
    float* c1 = (float*)(dsm + pad + 2 * STAGE_BYTES);
    float* c2 = c1 + 4096;

    int tid = threadIdx.x;
    for (int i = tid; i < 4096; i += 256) { c1[i] = 0.f; c2[i] = 0.f; }
    __syncthreads();

    int bid = blockIdx.x;
    int mo = (bid >> 4) * 128, no = (bid & 15) * 128;
    unsigned bt = 0;

    for (int t = 0; t < SEQ; t++) {
        // ---- layer 1: z = Z1[t] + h1@U1 ----
        {
            float acc[4][4][4];
#pragma unroll
            for (int a = 0; a < 4; a++)
#pragma unroll
                for (int b = 0; b < 4; b++)
#pragma unroll
                    for (int cc = 0; cc < 4; cc++) acc[a][b][cc] = 0.f;
            if (t > 0)   // t=0: h1 state is zero -> skip GEMM
                mma_mainloop(acc, sb, g_h1b[t & 1], nullptr, UNITS, g_U1b, UNITS, mo, no, 8);
            lstm_epilogue<1>(acc, t, mo, no, c1, g_h1b[(t + 1) & 1]);
        }
        grid_barrier(++bt);

        // ---- layer 2: z = b2 + [h1_new | h2_old] @ [W2;U2] ----
        {
            float acc[4][4][4];
#pragma unroll
            for (int a = 0; a < 4; a++)
#pragma unroll
                for (int b = 0; b < 4; b++)
#pragma unroll
                    for (int cc = 0; cc < 4; cc++) acc[a][b][cc] = 0.f;
            int nc2 = (t == 0) ? 8 : 16;   // t=0: h2 is zero -> only h1 half
            mma_mainloop(acc, sb, g_h1b[(t + 1) & 1], g_h2b[t & 1], UNITS, g_W2b, 2 * UNITS, mo, no, nc2);
            lstm_epilogue<2>(acc, t, mo, no, c2, g_h2b[(t + 1) & 1]);
        }
        grid_barrier(++bt);
    }
}

// ---------------- output projection ----------------
__global__ void out_kernel(const float* __restrict__ Wout, const float* __restrict__ bout,
                           float* __restrict__ out, int parity) {
    int gw = (blockIdx.x * blockDim.x + threadIdx.x) >> 5;
    int lane = threadIdx.x & 31;
    if (gw >= BATCH) return;
    const __nv_bfloat16* h = g_h2b[parity] + (size_t)gw * UNITS;
    float s = 0.f;
    for (int k = lane; k < UNITS; k += 32)
        s += __bfloat162float(h[k]) * Wout[k];
#pragma unroll
    for (int off = 16; off > 0; off >>= 1) s += __shfl_xor_sync(0xFFFFFFFF, s, off);
    if (lane == 0) out[gw] = __fdividef(1.f, 1.f + __expf(-(s + bout[0])));
}

// ---------------- launch ----------------
extern "C" void kernel_launch(void* const* d_in, const int* in_sizes, int n_in,
                              void* d_out, int out_size) {
    const int*   tokens = (const int*)d_in[0];
    const float* emb    = (const float*)d_in[1];
    const float* W1     = (const float*)d_in[2];
    const float* U1     = (const float*)d_in[3];
    const float* b1     = (const float*)d_in[4];
    const float* W2     = (const float*)d_in[5];
    const float* U2     = (const float*)d_in[6];
    const float* b2     = (const float*)d_in[7];
    const float* Wout   = (const float*)d_in[8];
    const float* bout   = (const float*)d_in[9];
    float* out = (float*)d_out;

    cudaFuncSetAttribute(pregemm_hmma_kernel, cudaFuncAttributeMaxDynamicSharedMemorySize, SMEM_PRE);
    cudaFuncSetAttribute(lstm_persist_kernel, cudaFuncAttributeMaxDynamicSharedMemorySize, SMEM_PERSIST);

    reset_kernel<<<1, 32>>>();
    prepack_kernel<<<N4, 256>>>(W1, U1, b1, W2, U2, b2);
    gather_kernel<<<ROWS, 128>>>(tokens, emb);
    pregemm_hmma_kernel<<<dim3(16, ROWS / 128), 256, SMEM_PRE>>>();
    lstm_persist_kernel<<<NBLK, 256, SMEM_PERSIST>>>();
    out_kernel<<<(BATCH * 32 + 255) / 256, 256>>>(Wout, bout, out, SEQ & 1);
}

// round 11
// speedup vs baseline: 3.0282x; 1.9746x over previous
#include <cuda_runtime.h>
#include <cuda_bf16.h>
#include <math.h>
#include <stdint.h>

// Problem constants
#define BATCH 1024
#define SEQ   80
#define UNITS 512
#define EMB   100
#define N4    2048
#define ROWS  (SEQ * BATCH)
#define KC    64               // K-chunk (64 bf16 = 128B rows)
#define NBLK  128              // persistent grid size (<=148 SMs -> all resident)
#define NTHR  512              // 16 warps

// ---------------- static device scratch ----------------
__device__ __nv_bfloat16 g_Xb[(size_t)ROWS * 128];     // gathered embeddings, bf16, padded K=128
__device__ float g_Z1[(size_t)ROWS * N4];              // x@W1 + b1 (reordered cols, fp32)
__device__ __nv_bfloat16 g_W1b[(size_t)N4 * 128];      // W1 reordered, [N][K] bf16, K padded
__device__ float g_b1r[N4];
__device__ float g_b2r[N4];
__device__ __nv_bfloat16 g_U1b[(size_t)N4 * UNITS];    // U1 reordered, [N][K]
__device__ __nv_bfloat16 g_W2b[(size_t)N4 * 2 * UNITS];// [W2;U2] reordered, [N][K]
__device__ __nv_bfloat16 g_h1b[2][(size_t)BATCH * UNITS];
__device__ __nv_bfloat16 g_h2b[2][(size_t)BATCH * UNITS];
__device__ unsigned g_bar_count;
__device__ unsigned g_bar_gen;

__device__ __forceinline__ float sigmoidf_(float x) { return __fdividef(1.0f, 1.0f + __expf(-x)); }

__device__ __forceinline__ uint32_t smem_u32(const void* p) {
    uint32_t a;
    asm("{ .reg .u64 t; cvta.to.shared.u64 t, %1; cvt.u32.u64 %0, t; }" : "=r"(a) : "l"(p));
    return a;
}
__device__ __forceinline__ uint32_t sw_off(uint32_t off) {
    return off ^ ((off >> 3) & 0x70);
}
__device__ __forceinline__ void ldmatrix_x4(uint32_t* r, uint32_t addr) {
    asm volatile("ldmatrix.sync.aligned.m8n8.x4.shared.b16 {%0,%1,%2,%3}, [%4];"
                 : "=r"(r[0]), "=r"(r[1]), "=r"(r[2]), "=r"(r[3]) : "r"(addr));
}
__device__ __forceinline__ void mma16816(float* c, const uint32_t* a, const uint32_t* b) {
    asm volatile("mma.sync.aligned.m16n8k16.row.col.f32.bf16.bf16.f32 "
                 "{%0,%1,%2,%3}, {%4,%5,%6,%7}, {%8,%9}, {%0,%1,%2,%3};"
                 : "+f"(c[0]), "+f"(c[1]), "+f"(c[2]), "+f"(c[3])
                 : "r"(a[0]), "r"(a[1]), "r"(a[2]), "r"(a[3]), "r"(b[0]), "r"(b[1]));
}
__device__ __forceinline__ void cp_async16(uint32_t dst, const void* src) {
    asm volatile("cp.async.cg.shared.global [%0], [%1], 16;" :: "r"(dst), "l"(src) : "memory");
}
#define CP_COMMIT()   asm volatile("cp.async.commit_group;" ::: "memory")
#define CP_WAIT(n)    asm volatile("cp.async.wait_group %0;" :: "n"(n) : "memory")

// ---------------- reset (per replay; determinism) ----------------
__global__ void reset_kernel() {
    if (threadIdx.x == 0) { g_bar_count = 0; g_bar_gen = 0; }
}

// ---------------- prepack: reorder (n = u*4+g) + bf16, [N][K] ----------------
__global__ void prepack_kernel(const float* __restrict__ W1, const float* __restrict__ U1,
                               const float* __restrict__ b1, const float* __restrict__ W2,
                               const float* __restrict__ U2, const float* __restrict__ b2) {
    int n = blockIdx.x;
    int u = n >> 2, gg = n & 3;
    int src = gg * UNITS + u;
    for (int k = threadIdx.x; k < 2 * UNITS; k += blockDim.x) {
        float w = (k < UNITS) ? W2[(size_t)k * N4 + src] : U2[(size_t)(k - UNITS) * N4 + src];
        g_W2b[(size_t)n * (2 * UNITS) + k] = __float2bfloat16(w);
        if (k < UNITS)
            g_U1b[(size_t)n * UNITS + k] = __float2bfloat16(U1[(size_t)k * N4 + src]);
        if (k < 128)
            g_W1b[(size_t)n * 128 + k] = __float2bfloat16(k < EMB ? W1[(size_t)k * N4 + src] : 0.f);
    }
    if (threadIdx.x == 0) { g_b1r[n] = b1[src]; g_b2r[n] = b2[src]; }
}

// ---------------- embedding gather (bf16, padded to 128 cols) ----------------
__global__ void gather_kernel(const int* __restrict__ tokens, const float* __restrict__ emb) {
    int row = blockIdx.x;
    int t = row / BATCH, b = row - t * BATCH;
    int tok = tokens[(size_t)b * SEQ + t];
    int e = threadIdx.x;
    g_Xb[(size_t)row * 128 + e] = __float2bfloat16(e < EMB ? emb[(size_t)tok * EMB + e] : 0.f);
}

// ---------------- shared HMMA mainloop: 128x128 tile, 16 warps (4M x 4N), warp tile 32x32 ----------------
// Stage (32KB): A 16K | B 16K. 2-stage cp.async; register double-buffered fragments.
#define STAGE_BYTES 32768

__device__ __forceinline__ void mma_mainloop(
    float (&acc)[2][4][4], uint32_t sb,
    const __nv_bfloat16* __restrict__ A0, const __nv_bfloat16* __restrict__ A1, int astride,
    const __nv_bfloat16* __restrict__ Bw, int bstride, int mo, int no, int nc)
{
    int tid = threadIdx.x, wid = tid >> 5, lane = tid & 31;
    int wm = wid >> 2, wn = wid & 3;
    int lr = tid >> 2, lq = (tid & 3) * 2;   // 4 threads per 128B row, 2 x 16B lines each

    auto load_chunk = [&](int i, uint32_t stage) {
        int k0 = i * KC;
        const __nv_bfloat16* asrc = (A1 != nullptr && k0 >= UNITS) ? A1 : A0;
        int kk0 = k0 & (UNITS - 1);
        const __nv_bfloat16* ap = asrc + (size_t)(mo + lr) * astride + kk0 + lq * 8;
        const __nv_bfloat16* bp = Bw + (size_t)(no + lr) * bstride + k0 + lq * 8;
#pragma unroll
        for (int q = 0; q < 2; q++) {
            uint32_t off = sw_off((uint32_t)(lr * 128 + (lq + q) * 16));
            cp_async16(stage + off,         ap + q * 8);
            cp_async16(stage + 16384 + off, bp + q * 8);
        }
        CP_COMMIT();
    };

    uint32_t a_rowoff[2];
#pragma unroll
    for (int mt = 0; mt < 2; mt++)
        a_rowoff[mt] = (uint32_t)((wm * 32 + mt * 16 + (lane & 15)) * 128 + (lane >> 4) * 16);
    uint32_t b_rowoff[2];
#pragma unroll
    for (int pr = 0; pr < 2; pr++)
        b_rowoff[pr] = (uint32_t)((wn * 32 + pr * 16 + ((lane >> 4) & 1) * 8 + (lane & 7)) * 128 + ((lane >> 3) & 1) * 16);

    load_chunk(0, sb);
    CP_WAIT(0);
    __syncthreads();

    for (int i = 0; i < nc; i++) {
        uint32_t cur = sb + (uint32_t)(i & 1) * STAGE_BYTES;
        uint32_t nxt = sb + (uint32_t)((i + 1) & 1) * STAGE_BYTES;

        if (i + 1 < nc)
            load_chunk(i + 1, nxt);   // gmem->smem overlaps MMA below

        uint32_t af[2][2][4], bf[2][2][4];   // [buf][mt/pr][4]
        // preload ks=0 fragments
#pragma unroll
        for (int mt = 0; mt < 2; mt++)
            ldmatrix_x4(af[0][mt], cur + sw_off(a_rowoff[mt]));
#pragma unroll
        for (int pr = 0; pr < 2; pr++)
            ldmatrix_x4(bf[0][pr], cur + 16384 + sw_off(b_rowoff[pr]));

#pragma unroll
        for (int ks = 0; ks < 4; ks++) {
            int cb = ks & 1, nb = (ks + 1) & 1;
            if (ks < 3) {   // prefetch ks+1 fragments while issuing MMAs for ks
#pragma unroll
                for (int mt = 0; mt < 2; mt++)
                    ldmatrix_x4(af[nb][mt], cur + sw_off(a_rowoff[mt] + (ks + 1) * 32));
#pragma unroll
                for (int pr = 0; pr < 2; pr++)
                    ldmatrix_x4(bf[nb][pr], cur + 16384 + sw_off(b_rowoff[pr] + (ks + 1) * 32));
            }
#pragma unroll
            for (int mt = 0; mt < 2; mt++)
#pragma unroll
                for (int nt = 0; nt < 4; nt++)
                    mma16816(acc[mt][nt], af[cb][mt], &bf[cb][nt >> 1][(nt & 1) * 2]);
        }

        if (i + 1 < nc) CP_WAIT(0);
        __syncthreads();
    }
}

// ---------------- pre-GEMM (bf16 HMMA): Z1 = Xb @ W1b + b1r ----------------
#define SMEM_PRE (1024 + 2 * STAGE_BYTES)

__global__ __launch_bounds__(NTHR) void pregemm_hmma_kernel() {
    extern __shared__ char dsm[];
    uint32_t raw = smem_u32(dsm);
    uint32_t sb = raw + ((1024u - (raw & 1023u)) & 1023u);

    int lane = threadIdx.x & 31, wid = threadIdx.x >> 5;
    int wm = wid >> 2, wn = wid & 3;
    int mo = blockIdx.y * 128, no = blockIdx.x * 128;

    float acc[2][4][4];
#pragma unroll
    for (int a = 0; a < 2; a++)
#pragma unroll
        for (int b = 0; b < 4; b++)
#pragma unroll
            for (int cc = 0; cc < 4; cc++) acc[a][b][cc] = 0.f;

    mma_mainloop(acc, sb, g_Xb, nullptr, 128, g_W1b, 128, mo, no, 2);

#pragma unroll
    for (int mt = 0; mt < 2; mt++)
#pragma unroll
        for (int nt = 0; nt < 4; nt++)
#pragma unroll
            for (int ri = 0; ri < 2; ri++) {
                float v0 = acc[mt][nt][2 * ri + 0];
                float v1 = acc[mt][nt][2 * ri + 1];
                float o0 = __shfl_xor_sync(0xFFFFFFFF, v0, 1);
                float o1 = __shfl_xor_sync(0xFFFFFFFF, v1, 1);
                if ((lane & 1) == 0) {
                    int row_l = wm * 32 + mt * 16 + (lane >> 2) + ri * 8;
                    int c_l = wn * 32 + nt * 8 + (lane & 3) * 2;   // multiple of 4
                    float4 bb = *(const float4*)(g_b1r + no + c_l);
                    float4 r = make_float4(v0 + bb.x, v1 + bb.y, o0 + bb.z, o1 + bb.w);
                    *(float4*)(g_Z1 + ((size_t)mo + row_l) * N4 + no + c_l) = r;
                }
            }
}

// ---------------- LSTM gate epilogue (c in SMEM, h -> global bf16) ----------------
template <int LAYER>
__device__ __forceinline__ void lstm_epilogue(
    float (&acc)[2][4][4], int t, int mo, int no,
    float* __restrict__ csm, __nv_bfloat16* __restrict__ hout)
{
    int lane = threadIdx.x & 31, wid = threadIdx.x >> 5;
    int wm = wid >> 2, wn = wid & 3;
#pragma unroll
    for (int mt = 0; mt < 2; mt++)
#pragma unroll
        for (int nt = 0; nt < 4; nt++)
#pragma unroll
            for (int ri = 0; ri < 2; ri++) {
                float v0 = acc[mt][nt][2 * ri + 0];
                float v1 = acc[mt][nt][2 * ri + 1];
                float o0 = __shfl_xor_sync(0xFFFFFFFF, v0, 1);
                float o1 = __shfl_xor_sync(0xFFFFFFFF, v1, 1);
                if ((lane & 1) == 0) {
                    int row_l = wm * 32 + mt * 16 + (lane >> 2) + ri * 8;
                    int c_l = wn * 32 + nt * 8 + (lane & 3) * 2;   // multiple of 4
                    const float* zp = (LAYER == 1)
                        ? (g_Z1 + ((size_t)t * BATCH + mo + row_l) * N4 + no + c_l)
                        : (g_b2r + no + c_l);
                    float4 zb = *(const float4*)zp;
                    float zi = v0 + zb.x, zf = v1 + zb.y;
                    float zg = o0 + zb.z, zo = o1 + zb.w;
                    float* cp = csm + row_l * 32 + (c_l >> 2);
                    float cn = sigmoidf_(zf) * (*cp) + sigmoidf_(zi) * tanhf(zg);
                    *cp = cn;
                    hout[(size_t)(mo + row_l) * UNITS + ((no + c_l) >> 2)] =
                        __float2bfloat16(sigmoidf_(zo) * tanhf(cn));
                }
            }
}

// ---------------- persistent LSTM kernel: all 80 steps, grid barrier ----------------
#define SMEM_PERSIST (1024 + 2 * STAGE_BYTES + 2 * 16384)

__device__ __forceinline__ void grid_barrier(unsigned target) {
    __threadfence();
    __syncthreads();
    if (threadIdx.x == 0) {
        unsigned ticket = atomicAdd(&g_bar_count, 1u);
        if (ticket == NBLK - 1) {
            atomicExch(&g_bar_count, 0u);
            __threadfence();
            atomicAdd(&g_bar_gen, 1u);
        } else {
            while (*(volatile unsigned*)&g_bar_gen < target) { }
            __threadfence();
        }
    }
    __syncthreads();
}

__global__ __launch_bounds__(NTHR, 1) void lstm_persist_kernel() {
    extern __shared__ char dsm[];
    uint32_t raw = smem_u32(dsm);
    uint32_t pad = (1024u - (raw & 1023u)) & 1023u;
    uint32_t sb = raw + pad;
    float* c1 = (float*)(dsm + pad + 2 * STAGE_BYTES);
    float* c2 = c1 + 4096;

    int tid = threadIdx.x;
    for (int i = tid; i < 4096; i += NTHR) { c1[i] = 0.f; c2[i] = 0.f; }
    __syncthreads();

    int bid = blockIdx.x;
    int mo = (bid >> 4) * 128, no = (bid & 15) * 128;
    unsigned bt = 0;

    for (int t = 0; t < SEQ; t++) {
        // ---- layer 1: z = Z1[t] + h1@U1 ----
        {
            float acc[2][4][4];
#pragma unroll
            for (int a = 0; a < 2; a++)
#pragma unroll
                for (int b = 0; b < 4; b++)
#pragma unroll
                    for (int cc = 0; cc < 4; cc++) acc[a][b][cc] = 0.f;
            if (t > 0)   // t=0: h1 state is zero -> skip GEMM
                mma_mainloop(acc, sb, g_h1b[t & 1], nullptr, UNITS, g_U1b, UNITS, mo, no, 8);
            lstm_epilogue<1>(acc, t, mo, no, c1, g_h1b[(t + 1) & 1]);
        }
        grid_barrier(++bt);

        // ---- layer 2: z = b2 + [h1_new | h2_old] @ [W2;U2] ----
        {
            float acc[2][4][4];
#pragma unroll
            for (int a = 0; a < 2; a++)
#pragma unroll
                for (int b = 0; b < 4; b++)
#pragma unroll
                    for (int cc = 0; cc < 4; cc++) acc[a][b][cc] = 0.f;
            int nc2 = (t == 0) ? 8 : 16;   // t=0: h2 is zero -> only h1 half
            mma_mainloop(acc, sb, g_h1b[(t + 1) & 1], g_h2b[t & 1], UNITS, g_W2b, 2 * UNITS, mo, no, nc2);
            lstm_epilogue<2>(acc, t, mo, no, c2, g_h2b[(t + 1) & 1]);
        }
        grid_barrier(++bt);
    }
}

// ---------------- output projection ----------------
__global__ void out_kernel(const float* __restrict__ Wout, const float* __restrict__ bout,
                           float* __restrict__ out, int parity) {
    int gw = (blockIdx.x * blockDim.x + threadIdx.x) >> 5;
    int lane = threadIdx.x & 31;
    if (gw >= BATCH) return;
    const __nv_bfloat16* h = g_h2b[parity] + (size_t)gw * UNITS;
    float s = 0.f;
    for (int k = lane; k < UNITS; k += 32)
        s += __bfloat162float(h[k]) * Wout[k];
#pragma unroll
    for (int off = 16; off > 0; off >>= 1) s += __shfl_xor_sync(0xFFFFFFFF, s, off);
    if (lane == 0) out[gw] = __fdividef(1.f, 1.f + __expf(-(s + bout[0])));
}

// ---------------- launch ----------------
extern "C" void kernel_launch(void* const* d_in, const int* in_sizes, int n_in,
                              void* d_out, int out_size) {
    const int*   tokens = (const int*)d_in[0];
    const float* emb    = (const float*)d_in[1];
    const float* W1     = (const float*)d_in[2];
    const float* U1     = (const float*)d_in[3];
    const float* b1     = (const float*)d_in[4];
    const float* W2     = (const float*)d_in[5];
    const float* U2     = (const float*)d_in[6];
    const float* b2     = (const float*)d_in[7];
    const float* Wout   = (const float*)d_in[8];
    const float* bout   = (const float*)d_in[9];
    float* out = (float*)d_out;

    cudaFuncSetAttribute(pregemm_hmma_kernel, cudaFuncAttributeMaxDynamicSharedMemorySize, SMEM_PRE);
    cudaFuncSetAttribute(lstm_persist_kernel, cudaFuncAttributeMaxDynamicSharedMemorySize, SMEM_PERSIST);

    reset_kernel<<<1, 32>>>();
    prepack_kernel<<<N4, 256>>>(W1, U1, b1, W2, U2, b2);
    gather_kernel<<<ROWS, 128>>>(tokens, emb);
    pregemm_hmma_kernel<<<dim3(16, ROWS / 128), NTHR, SMEM_PRE>>>();
    lstm_persist_kernel<<<NBLK, NTHR, SMEM_PERSIST>>>();
    out_kernel<<<(BATCH * 32 + 255) / 256, 256>>>(Wout, bout, out, SEQ & 1);
}

// round 12
// speedup vs baseline: 3.0350x; 1.0023x over previous
#include <cuda_runtime.h>
#include <cuda_bf16.h>
#include <math.h>
#include <stdint.h>

// Problem constants
#define BATCH 1024
#define SEQ   80
#define UNITS 512
#define EMB   100
#define N4    2048
#define ROWS  (SEQ * BATCH)
#define KC    128              // K-chunk (two 64-k sub-tiles per stage)
#define NBLK  128              // persistent grid size (<=148 SMs -> all resident)
#define NTHR  512              // 16 warps

// ---------------- static device scratch ----------------
__device__ __nv_bfloat16 g_Xb[(size_t)ROWS * 128];     // gathered embeddings, bf16, padded K=128
__device__ float g_Z1[(size_t)ROWS * N4];              // x@W1 + b1 (reordered cols, fp32)
__device__ __nv_bfloat16 g_W1b[(size_t)N4 * 128];      // W1 reordered, [N][K] bf16, K padded
__device__ float g_b1r[N4];
__device__ float g_b2r[N4];
__device__ __nv_bfloat16 g_U1b[(size_t)N4 * UNITS];    // U1 reordered, [N][K]
__device__ __nv_bfloat16 g_W2b[(size_t)N4 * 2 * UNITS];// [W2;U2] reordered, [N][K]
__device__ __nv_bfloat16 g_h1b[2][(size_t)BATCH * UNITS];
__device__ __nv_bfloat16 g_h2b[2][(size_t)BATCH * UNITS];
__device__ unsigned g_bar_count;
__device__ unsigned g_bar_gen;

__device__ __forceinline__ float tanh_f(float x) {
    float r;
    asm("tanh.approx.f32 %0, %1;" : "=f"(r) : "f"(x));
    return r;
}
__device__ __forceinline__ float sigmoidf_(float x) { return fmaf(0.5f, tanh_f(0.5f * x), 0.5f); }

__device__ __forceinline__ uint32_t smem_u32(const void* p) {
    uint32_t a;
    asm("{ .reg .u64 t; cvta.to.shared.u64 t, %1; cvt.u32.u64 %0, t; }" : "=r"(a) : "l"(p));
    return a;
}
__device__ __forceinline__ uint32_t sw_off(uint32_t off) {
    return off ^ ((off >> 3) & 0x70);
}
__device__ __forceinline__ void ldmatrix_x4(uint32_t* r, uint32_t addr) {
    asm volatile("ldmatrix.sync.aligned.m8n8.x4.shared.b16 {%0,%1,%2,%3}, [%4];"
                 : "=r"(r[0]), "=r"(r[1]), "=r"(r[2]), "=r"(r[3]) : "r"(addr));
}
__device__ __forceinline__ void mma16816(float* c, const uint32_t* a, const uint32_t* b) {
    asm volatile("mma.sync.aligned.m16n8k16.row.col.f32.bf16.bf16.f32 "
                 "{%0,%1,%2,%3}, {%4,%5,%6,%7}, {%8,%9}, {%0,%1,%2,%3};"
                 : "+f"(c[0]), "+f"(c[1]), "+f"(c[2]), "+f"(c[3])
                 : "r"(a[0]), "r"(a[1]), "r"(a[2]), "r"(a[3]), "r"(b[0]), "r"(b[1]));
}
__device__ __forceinline__ void cp_async16(uint32_t dst, const void* src) {
    asm volatile("cp.async.cg.shared.global [%0], [%1], 16;" :: "r"(dst), "l"(src) : "memory");
}
#define CP_COMMIT()   asm volatile("cp.async.commit_group;" ::: "memory")
#define CP_WAIT(n)    asm volatile("cp.async.wait_group %0;" :: "n"(n) : "memory")

// ---------------- reset (per replay; determinism) ----------------
__global__ void reset_kernel() {
    if (threadIdx.x == 0) { g_bar_count = 0; g_bar_gen = 0; }
}

// ---------------- prepack: reorder (n = u*4+g) + bf16, [N][K] ----------------
__global__ void prepack_kernel(const float* __restrict__ W1, const float* __restrict__ U1,
                               const float* __restrict__ b1, const float* __restrict__ W2,
                               const float* __restrict__ U2, const float* __restrict__ b2) {
    int n = blockIdx.x;
    int u = n >> 2, gg = n & 3;
    int src = gg * UNITS + u;
    for (int k = threadIdx.x; k < 2 * UNITS; k += blockDim.x) {
        float w = (k < UNITS) ? W2[(size_t)k * N4 + src] : U2[(size_t)(k - UNITS) * N4 + src];
        g_W2b[(size_t)n * (2 * UNITS) + k] = __float2bfloat16(w);
        if (k < UNITS)
            g_U1b[(size_t)n * UNITS + k] = __float2bfloat16(U1[(size_t)k * N4 + src]);
        if (k < 128)
            g_W1b[(size_t)n * 128 + k] = __float2bfloat16(k < EMB ? W1[(size_t)k * N4 + src] : 0.f);
    }
    if (threadIdx.x == 0) { g_b1r[n] = b1[src]; g_b2r[n] = b2[src]; }
}

// ---------------- embedding gather (bf16, padded to 128 cols) ----------------
__global__ void gather_kernel(const int* __restrict__ tokens, const float* __restrict__ emb) {
    int row = blockIdx.x;
    int t = row / BATCH, b = row - t * BATCH;
    int tok = tokens[(size_t)b * SEQ + t];
    int e = threadIdx.x;
    g_Xb[(size_t)row * 128 + e] = __float2bfloat16(e < EMB ? emb[(size_t)tok * EMB + e] : 0.f);
}

// ---------------- shared HMMA mainloop: 128x128 tile, 16 warps (4M x 4N), warp tile 32x32 ----------------
// Stage (64KB): A sub0 16K | A sub1 16K | B sub0 16K | B sub1 16K (sub = 64-k half).
// 2-stage cp.async; register double-buffered fragments across 8 k16 steps.
#define STAGE_BYTES 65536

__device__ __forceinline__ void mma_mainloop(
    float (&acc)[2][4][4], uint32_t sb,
    const __nv_bfloat16* __restrict__ A0, const __nv_bfloat16* __restrict__ A1, int astride,
    const __nv_bfloat16* __restrict__ Bw, int bstride, int mo, int no, int nc)
{
    int tid = threadIdx.x, wid = tid >> 5, lane = tid & 31;
    int wm = wid >> 2, wn = wid & 3;
    int lr = tid >> 2, lq = (tid & 3) * 2;   // 4 threads per 128B row, 2 x 16B lines each

    auto load_chunk = [&](int i, uint32_t stage) {
        int k0 = i * KC;
        const __nv_bfloat16* asrc = (A1 != nullptr && k0 >= UNITS) ? A1 : A0;
        int kk0 = k0 & (UNITS - 1);
        const __nv_bfloat16* ap = asrc + (size_t)(mo + lr) * astride + kk0;
        const __nv_bfloat16* bp = Bw + (size_t)(no + lr) * bstride + k0;
#pragma unroll
        for (int sub = 0; sub < 2; sub++) {
#pragma unroll
            for (int q = 0; q < 2; q++) {
                uint32_t off = sw_off((uint32_t)(lr * 128 + (lq + q) * 16)) + (uint32_t)sub * 16384;
                cp_async16(stage + off,         ap + sub * 64 + (lq + q) * 8);
                cp_async16(stage + 32768 + off, bp + sub * 64 + (lq + q) * 8);
            }
        }
        CP_COMMIT();
    };

    uint32_t a_rowoff[2];
#pragma unroll
    for (int mt = 0; mt < 2; mt++)
        a_rowoff[mt] = (uint32_t)((wm * 32 + mt * 16 + (lane & 15)) * 128 + (lane >> 4) * 16);
    uint32_t b_rowoff[2];
#pragma unroll
    for (int pr = 0; pr < 2; pr++)
        b_rowoff[pr] = (uint32_t)((wn * 32 + pr * 16 + ((lane >> 4) & 1) * 8 + (lane & 7)) * 128 + ((lane >> 3) & 1) * 16);

    load_chunk(0, sb);
    CP_WAIT(0);
    __syncthreads();

    for (int i = 0; i < nc; i++) {
        uint32_t cur = sb + (uint32_t)(i & 1) * STAGE_BYTES;
        uint32_t nxt = sb + (uint32_t)((i + 1) & 1) * STAGE_BYTES;

        if (i + 1 < nc)
            load_chunk(i + 1, nxt);   // gmem->smem overlaps MMA below

        uint32_t af[2][2][4], bf[2][2][4];   // [buf][mt/pr][4]
        // preload ks=0 fragments
#pragma unroll
        for (int mt = 0; mt < 2; mt++)
            ldmatrix_x4(af[0][mt], cur + sw_off(a_rowoff[mt]));
#pragma unroll
        for (int pr = 0; pr < 2; pr++)
            ldmatrix_x4(bf[0][pr], cur + 32768 + sw_off(b_rowoff[pr]));

#pragma unroll
        for (int ks = 0; ks < 8; ks++) {
            int cb = ks & 1, nb = (ks + 1) & 1;
            if (ks < 7) {   // prefetch ks+1 fragments while issuing MMAs for ks
                uint32_t nsub = (uint32_t)((ks + 1) >> 2) * 16384;
                uint32_t nkof = (uint32_t)((ks + 1) & 3) * 32;
#pragma unroll
                for (int mt = 0; mt < 2; mt++)
                    ldmatrix_x4(af[nb][mt], cur + nsub + sw_off(a_rowoff[mt] + nkof));
#pragma unroll
                for (int pr = 0; pr < 2; pr++)
                    ldmatrix_x4(bf[nb][pr], cur + 32768 + nsub + sw_off(b_rowoff[pr] + nkof));
            }
#pragma unroll
            for (int mt = 0; mt < 2; mt++)
#pragma unroll
                for (int nt = 0; nt < 4; nt++)
                    mma16816(acc[mt][nt], af[cb][mt], &bf[cb][nt >> 1][(nt & 1) * 2]);
        }

        if (i + 1 < nc) CP_WAIT(0);
        __syncthreads();
    }
}

// ---------------- pre-GEMM (bf16 HMMA): Z1 = Xb @ W1b + b1r ----------------
#define SMEM_PRE (1024 + STAGE_BYTES)

__global__ __launch_bounds__(NTHR) void pregemm_hmma_kernel() {
    extern __shared__ char dsm[];
    uint32_t raw = smem_u32(dsm);
    uint32_t sb = raw + ((1024u - (raw & 1023u)) & 1023u);

    int lane = threadIdx.x & 31, wid = threadIdx.x >> 5;
    int wm = wid >> 2, wn = wid & 3;
    int mo = blockIdx.y * 128, no = blockIdx.x * 128;

    float acc[2][4][4];
#pragma unroll
    for (int a = 0; a < 2; a++)
#pragma unroll
        for (int b = 0; b < 4; b++)
#pragma unroll
            for (int cc = 0; cc < 4; cc++) acc[a][b][cc] = 0.f;

    mma_mainloop(acc, sb, g_Xb, nullptr, 128, g_W1b, 128, mo, no, 1);

#pragma unroll
    for (int mt = 0; mt < 2; mt++)
#pragma unroll
        for (int nt = 0; nt < 4; nt++)
#pragma unroll
            for (int ri = 0; ri < 2; ri++) {
                float v0 = acc[mt][nt][2 * ri + 0];
                float v1 = acc[mt][nt][2 * ri + 1];
                float o0 = __shfl_xor_sync(0xFFFFFFFF, v0, 1);
                float o1 = __shfl_xor_sync(0xFFFFFFFF, v1, 1);
                if ((lane & 1) == 0) {
                    int row_l = wm * 32 + mt * 16 + (lane >> 2) + ri * 8;
                    int c_l = wn * 32 + nt * 8 + (lane & 3) * 2;   // multiple of 4
                    float4 bb = *(const float4*)(g_b1r + no + c_l);
                    float4 r = make_float4(v0 + bb.x, v1 + bb.y, o0 + bb.z, o1 + bb.w);
                    *(float4*)(g_Z1 + ((size_t)mo + row_l) * N4 + no + c_l) = r;
                }
            }
}

// ---------------- LSTM gate epilogue (c in SMEM, h -> global bf16) ----------------
template <int LAYER>
__device__ __forceinline__ void lstm_epilogue(
    float (&acc)[2][4][4], int t, int mo, int no,
    float* __restrict__ csm, __nv_bfloat16* __restrict__ hout)
{
    int lane = threadIdx.x & 31, wid = threadIdx.x >> 5;
    int wm = wid >> 2, wn = wid & 3;
#pragma unroll
    for (int mt = 0; mt < 2; mt++)
#pragma unroll
        for (int nt = 0; nt < 4; nt++)
#pragma unroll
            for (int ri = 0; ri < 2; ri++) {
                float v0 = acc[mt][nt][2 * ri + 0];
                float v1 = acc[mt][nt][2 * ri + 1];
                float o0 = __shfl_xor_sync(0xFFFFFFFF, v0, 1);
                float o1 = __shfl_xor_sync(0xFFFFFFFF, v1, 1);
                if ((lane & 1) == 0) {
                    int row_l = wm * 32 + mt * 16 + (lane >> 2) + ri * 8;
                    int c_l = wn * 32 + nt * 8 + (lane & 3) * 2;   // multiple of 4
                    const float* zp = (LAYER == 1)
                        ? (g_Z1 + ((size_t)t * BATCH + mo + row_l) * N4 + no + c_l)
                        : (g_b2r + no + c_l);
                    float4 zb = *(const float4*)zp;
                    float zi = v0 + zb.x, zf = v1 + zb.y;
                    float zg = o0 + zb.z, zo = o1 + zb.w;
                    float* cp = csm + row_l * 32 + (c_l >> 2);
                    float cn = sigmoidf_(zf) * (*cp) + sigmoidf_(zi) * tanh_f(zg);
                    *cp = cn;
                    hout[(size_t)(mo + row_l) * UNITS + ((no + c_l) >> 2)] =
                        __float2bfloat16(sigmoidf_(zo) * tanh_f(cn));
                }
            }
}

// ---------------- persistent LSTM kernel: all 80 steps, grid barrier ----------------
#define SMEM_PERSIST (1024 + 2 * STAGE_BYTES + 2 * 16384)

__device__ __forceinline__ void grid_barrier(unsigned target) {
    __threadfence();
    __syncthreads();
    if (threadIdx.x == 0) {
        unsigned ticket = atomicAdd(&g_bar_count, 1u);
        if (ticket == NBLK - 1) {
            atomicExch(&g_bar_count, 0u);
            __threadfence();
            atomicAdd(&g_bar_gen, 1u);
        } else {
            while (*(volatile unsigned*)&g_bar_gen < target) { }
            __threadfence();
        }
    }
    __syncthreads();
}

__global__ __launch_bounds__(NTHR, 1) void lstm_persist_kernel() {
    extern __shared__ char dsm[];
    uint32_t raw = smem_u32(dsm);
    uint32_t pad = (1024u - (raw & 1023u)) & 1023u;
    uint32_t sb = raw + pad;
    float* c1 = (float*)(dsm + pad + 2 * STAGE_BYTES);
    float* c2 = c1 + 4096;

    int tid = threadIdx.x;
    for (int i = tid; i < 4096; i += NTHR) { c1[i] = 0.f; c2[i] = 0.f; }
    __syncthreads();

    int bid = blockIdx.x;
    int mo = (bid >> 4) * 128, no = (bid & 15) * 128;
    unsigned bt = 0;

    for (int t = 0; t < SEQ; t++) {
        // ---- layer 1: z = Z1[t] + h1@U1 ----
        {
            float acc[2][4][4];
#pragma unroll
            for (int a = 0; a < 2; a++)
#pragma unroll
                for (int b = 0; b < 4; b++)
#pragma unroll
                    for (int cc = 0; cc < 4; cc++) acc[a][b][cc] = 0.f;
            if (t > 0)   // t=0: h1 state is zero -> skip GEMM
                mma_mainloop(acc, sb, g_h1b[t & 1], nullptr, UNITS, g_U1b, UNITS, mo, no, 4);
            lstm_epilogue<1>(acc, t, mo, no, c1, g_h1b[(t + 1) & 1]);
        }
        grid_barrier(++bt);

        // ---- layer 2: z = b2 + [h1_new | h2_old] @ [W2;U2] ----
        {
            float acc[2][4][4];
#pragma unroll
            for (int a = 0; a < 2; a++)
#pragma unroll
                for (int b = 0; b < 4; b++)
#pragma unroll
                    for (int cc = 0; cc < 4; cc++) acc[a][b][cc] = 0.f;
            int nc2 = (t == 0) ? 4 : 8;   // t=0: h2 is zero -> only h1 half
            mma_mainloop(acc, sb, g_h1b[(t + 1) & 1], g_h2b[t & 1], UNITS, g_W2b, 2 * UNITS, mo, no, nc2);
            lstm_epilogue<2>(acc, t, mo, no, c2, g_h2b[(t + 1) & 1]);
        }
        grid_barrier(++bt);
    }
}

// ---------------- output projection ----------------
__global__ void out_kernel(const float* __restrict__ Wout, const float* __restrict__ bout,
                           float* __restrict__ out, int parity) {
    int gw = (blockIdx.x * blockDim.x + threadIdx.x) >> 5;
    int lane = threadIdx.x & 31;
    if (gw >= BATCH) return;
    const __nv_bfloat16* h = g_h2b[parity] + (size_t)gw * UNITS;
    float s = 0.f;
    for (int k = lane; k < UNITS; k += 32)
        s += __bfloat162float(h[k]) * Wout[k];
#pragma unroll
    for (int off = 16; off > 0; off >>= 1) s += __shfl_xor_sync(0xFFFFFFFF, s, off);
    if (lane == 0) out[gw] = __fdividef(1.f, 1.f + __expf(-(s + bout[0])));
}

// ---------------- launch ----------------
extern "C" void kernel_launch(void* const* d_in, const int* in_sizes, int n_in,
                              void* d_out, int out_size) {
    const int*   tokens = (const int*)d_in[0];
    const float* emb    = (const float*)d_in[1];
    const float* W1     = (const float*)d_in[2];
    const float* U1     = (const float*)d_in[3];
    const float* b1     = (const float*)d_in[4];
    const float* W2     = (const float*)d_in[5];
    const float* U2     = (const float*)d_in[6];
    const float* b2     = (const float*)d_in[7];
    const float* Wout   = (const float*)d_in[8];
    const float* bout   = (const float*)d_in[9];
    float* out = (float*)d_out;

    cudaFuncSetAttribute(pregemm_hmma_kernel, cudaFuncAttributeMaxDynamicSharedMemorySize, SMEM_PRE);
    cudaFuncSetAttribute(lstm_persist_kernel, cudaFuncAttributeMaxDynamicSharedMemorySize, SMEM_PERSIST);

    reset_kernel<<<1, 32>>>();
    prepack_kernel<<<N4, 256>>>(W1, U1, b1, W2, U2, b2);
    gather_kernel<<<ROWS, 128>>>(tokens, emb);
    pregemm_hmma_kernel<<<dim3(16, ROWS / 128), NTHR, SMEM_PRE>>>();
    lstm_persist_kernel<<<NBLK, NTHR, SMEM_PERSIST>>>();
    out_kernel<<<(BATCH * 32 + 255) / 256, 256>>>(Wout, bout, out, SEQ & 1);
}